// round 2
// baseline (speedup 1.0000x reference)
#include <cuda_runtime.h>
#include <math.h>

#define N_NODES 20000
#define N_EDGES 320000
#define E_TOT   340000   // edges + self loops
#define NFEAT   128
#define NHID    64
#define HEADS   4
#define HH      256      // HEADS*NHID
#define NCLASS  16

// softplus(1.0)
#define SP1 1.3132616875182228f

// ---------------- scratch (device globals, no allocation) ----------------
__device__ int      g_is64;
__device__ int      g_src[N_EDGES];
__device__ int      g_dst[N_EDGES];
__device__ float    g_X[N_NODES*NHID];
__device__ float    g_Y[N_NODES*NHID];
__device__ float    g_h[N_NODES*HH];
__device__ float    g_asrc[N_NODES*HEADS];
__device__ float    g_adst[N_NODES*HEADS];
__device__ unsigned g_emax[N_NODES*HEADS];   // order-encoded float for atomicMax
__device__ float    g_denom[N_NODES*HEADS];
__device__ float    g_acc[N_NODES*HH];       // weighted message accumulator

// ordered-uint encoding so unsigned atomicMax == float max
__device__ __forceinline__ unsigned enc_f(float f){
    unsigned u = __float_as_uint(f);
    return u ^ (((int)u >> 31) | 0x80000000u);
}
__device__ __forceinline__ float dec_f(unsigned k){
    unsigned u = (k & 0x80000000u) ? (k ^ 0x80000000u) : ~k;
    return __uint_as_float(u);
}

// ---------------- dtype detection + edge decode ----------------
// If edge_index is int64 (values < 2^31), every odd 32-bit word of the first
// 128 words is 0. For int32 inputs those words are random node ids.
__global__ void k_detect(const unsigned* __restrict__ w){
    if (threadIdx.x == 0){
        int all0 = 1;
        for (int i = 1; i < 128; i += 2) if (w[i] != 0u) all0 = 0;
        g_is64 = all0;
    }
}

__global__ void k_decode(const int* __restrict__ w){
    int e = blockIdx.x * blockDim.x + threadIdx.x;
    if (e >= N_EDGES) return;
    if (g_is64){
        g_src[e] = w[2*e];
        g_dst[e] = w[2*(N_EDGES + e)];
    } else {
        g_src[e] = w[e];
        g_dst[e] = w[N_EDGES + e];
    }
}

// ---------------- encoder: Y = relu(x @ W_enc + b_enc); X = Y ----------------
// 8 nodes per block, 64 threads (thread = hidden unit)
__global__ void k_encoder(const float* __restrict__ x,
                          const float* __restrict__ We,
                          const float* __restrict__ be){
    int nb = blockIdx.x * 8;
    int t  = threadIdx.x;
    __shared__ float xs[8][NFEAT];
    for (int r = t; r < 8*NFEAT; r += 64)
        xs[r >> 7][r & 127] = x[(nb + (r >> 7)) * NFEAT + (r & 127)];
    __syncthreads();
    float acc[8];
    float b = be[t];
#pragma unroll
    for (int m = 0; m < 8; m++) acc[m] = b;
    for (int k = 0; k < NFEAT; k++){
        float w = We[k * NHID + t];
#pragma unroll
        for (int m = 0; m < 8; m++) acc[m] = fmaf(xs[m][k], w, acc[m]);
    }
#pragma unroll
    for (int m = 0; m < 8; m++){
        float v = fmaxf(acc[m], 0.f);
        g_Y[(nb + m) * NHID + t] = v;
        g_X[(nb + m) * NHID + t] = v;
    }
}

// ---------------- per-layer projection: h = X @ W_gat, a_src, a_dst ----------------
// 8 nodes per block, 256 threads (thread = output column j = head*64+f)
__global__ void k_gat_proj(const float* __restrict__ Wg,
                           const float* __restrict__ atts,
                           const float* __restrict__ attd){
    int nb = blockIdx.x * 8;
    int t  = threadIdx.x;
    __shared__ float xs[8][NHID];
    __shared__ float sps[8][HH];
    __shared__ float spd[8][HH];
    for (int r = t; r < 8*NHID; r += 256)
        xs[r >> 6][r & 63] = g_X[(nb + (r >> 6)) * NHID + (r & 63)];
    __syncthreads();
    float acc[8] = {0,0,0,0,0,0,0,0};
    for (int k = 0; k < NHID; k++){
        float w = Wg[k * HH + t];
#pragma unroll
        for (int m = 0; m < 8; m++) acc[m] = fmaf(xs[m][k], w, acc[m]);
    }
    float as_ = atts[t], ad_ = attd[t];
#pragma unroll
    for (int m = 0; m < 8; m++){
        g_h[(nb + m) * HH + t] = acc[m];
        sps[m][t] = acc[m] * as_;
        spd[m][t] = acc[m] * ad_;
    }
    __syncthreads();
    // warp w reduces node m=w, all 4 heads
    int w = t >> 5, l = t & 31;
#pragma unroll
    for (int h = 0; h < HEADS; h++){
        float v1 = sps[w][h*64 + l] + sps[w][h*64 + 32 + l];
        float v2 = spd[w][h*64 + l] + spd[w][h*64 + 32 + l];
#pragma unroll
        for (int s = 16; s > 0; s >>= 1){
            v1 += __shfl_down_sync(0xffffffffu, v1, s);
            v2 += __shfl_down_sync(0xffffffffu, v2, s);
        }
        if (l == 0){
            g_asrc[(nb + w) * HEADS + h] = v1;
            g_adst[(nb + w) * HEADS + h] = v2;
        }
    }
}

// ---------------- init accumulators for one layer ----------------
__global__ void k_init(){
    int gid = blockIdx.x * blockDim.x + threadIdx.x;
    if (gid < N_NODES * HH) g_acc[gid] = 0.f;
    if (gid < N_NODES * HEADS){ g_denom[gid] = 0.f; g_emax[gid] = 0u; }
}

// ---------------- pass 1: segment max of leaky_relu(a_src[s]+a_dst[d]) ----------------
__global__ void k_edge_max(){
    int gid = blockIdx.x * blockDim.x + threadIdx.x;
    if (gid >= E_TOT * HEADS) return;
    int e = gid >> 2, h = gid & 3;
    int s, d;
    if (e < N_EDGES){ s = g_src[e]; d = g_dst[e]; }
    else            { s = d = e - N_EDGES; }
    float v = g_asrc[s * HEADS + h] + g_adst[d * HEADS + h];
    v = (v > 0.f) ? v : 0.2f * v;
    atomicMax(&g_emax[d * HEADS + h], enc_f(v));
}

// ---------------- pass 2: accumulate exp weights + weighted messages ----------------
// one block = one edge, 256 threads = head*64+f
__global__ void k_edge_accum(){
    int e = blockIdx.x;
    int t = threadIdx.x;
    __shared__ int ss, sd;
    if (t == 0){
        if (e < N_EDGES){ ss = g_src[e]; sd = g_dst[e]; }
        else            { ss = sd = e - N_EDGES; }
    }
    __syncthreads();
    int s = ss, d = sd;
    int h = t >> 6;
    float v = g_asrc[s * HEADS + h] + g_adst[d * HEADS + h];
    v = (v > 0.f) ? v : 0.2f * v;
    float em = dec_f(g_emax[d * HEADS + h]);
    float ex = __expf(v - em);
    atomicAdd(&g_acc[d * HH + t], g_h[s * HH + t] * ex);
    if ((t & 63) == 0) atomicAdd(&g_denom[d * HEADS + h], ex);
}

// ---------------- node update: elu, head-group mean, GraphCON step, rms norms ----------------
__global__ void k_node_update(const float* __restrict__ bg){
    int n = blockIdx.x, i = threadIdx.x;  // 64 threads
    float dn[HEADS];
#pragma unroll
    for (int h = 0; h < HEADS; h++) dn[h] = g_denom[n * HEADS + h] + 1e-16f;
    float aggv = 0.f;
#pragma unroll
    for (int k = 0; k < 4; k++){
        int c = i * 4 + k;
        int h = c >> 6;
        float cv = g_acc[n * HH + c] / dn[h] + bg[c];
        cv = (cv > 0.f) ? cv : (__expf(cv) - 1.f);   // elu
        aggv += cv;
    }
    aggv *= 0.25f;
    float y = g_Y[n * NHID + i];
    float x = g_X[n * NHID + i];
    // Y += DT*(Ks*agg - 2*zeta*omega*Y - omega^2*X), DT=1
    float yn = y + (SP1 * aggv - 2.f * SP1 * SP1 * y - SP1 * SP1 * x);
    float xn = x + yn;
    __shared__ float sx[NHID], sy[NHID];
    sx[i] = xn * xn; sy[i] = yn * yn;
    __syncthreads();
#pragma unroll
    for (int s = 32; s > 0; s >>= 1){
        if (i < s){ sx[i] += sx[i + s]; sy[i] += sy[i + s]; }
        __syncthreads();
    }
    float rx = rsqrtf(sx[0] * (1.f / NHID) + 1e-5f);
    float ry = rsqrtf(sy[0] * (1.f / NHID) + 1e-5f);
    g_X[n * NHID + i] = xn * rx;
    g_Y[n * NHID + i] = yn * ry;
}

// ---------------- decoder: out = X @ W_dec + b_dec ----------------
__global__ void k_decoder(const float* __restrict__ Wd,
                          const float* __restrict__ bd,
                          float* __restrict__ out){
    int gid = blockIdx.x * blockDim.x + threadIdx.x;
    if (gid >= N_NODES * NCLASS) return;
    int n = gid >> 4, j = gid & 15;
    float acc = bd[j];
#pragma unroll
    for (int k = 0; k < NHID; k++)
        acc = fmaf(g_X[n * NHID + k], Wd[k * NCLASS + j], acc);
    out[gid] = acc;
}

extern "C" void kernel_launch(void* const* d_in, const int* in_sizes, int n_in,
                              void* d_out, int out_size){
    const float* x    = (const float*)d_in[0];
    const void*  ei   = d_in[1];
    const float* We   = (const float*)d_in[2];
    const float* be   = (const float*)d_in[3];
    const float* Wg   = (const float*)d_in[4];
    const float* atts = (const float*)d_in[5];
    const float* attd = (const float*)d_in[6];
    const float* bg   = (const float*)d_in[7];
    const float* Wd   = (const float*)d_in[8];
    const float* bd   = (const float*)d_in[9];
    float* out = (float*)d_out;

    k_detect<<<1, 32>>>((const unsigned*)ei);
    k_decode<<<(N_EDGES + 255)/256, 256>>>((const int*)ei);

    k_encoder<<<N_NODES/8, 64>>>(x, We, be);
    for (int l = 0; l < 3; l++){
        k_init<<<(N_NODES*HH + 255)/256, 256>>>();
        k_gat_proj<<<N_NODES/8, 256>>>(Wg, atts, attd);
        k_edge_max<<<(E_TOT*HEADS + 255)/256, 256>>>();
        k_edge_accum<<<E_TOT, 256>>>();
        k_node_update<<<N_NODES, 64>>>(bg);
    }
    k_decoder<<<(N_NODES*NCLASS + 255)/256, 256>>>(Wd, bd, out);
}

// round 3
// speedup vs baseline: 2.0540x; 2.0540x over previous
#include <cuda_runtime.h>
#include <math.h>

#define N_NODES 20000
#define N_EDGES 320000
#define E_TOT   340000   // edges + self loops
#define NFEAT   128
#define NHID    64
#define HEADS   4
#define HH      256      // HEADS*NHID
#define NCLASS  16

// softplus(1.0)
#define SP1 1.3132616875182228f

// ---------------- scratch (device globals, no allocation) ----------------
__device__ int      g_is64;
__device__ int      g_src[E_TOT];
__device__ int      g_dst[E_TOT];
__device__ int      g_deg[N_NODES];
__device__ int      g_rowptr[N_NODES + 1];
__device__ int      g_cursor[N_NODES];
__device__ int      g_csrc[E_TOT];          // CSR-by-destination source list
__device__ float    g_X[N_NODES*NHID];
__device__ float    g_Y[N_NODES*NHID];
__device__ float    g_h[N_NODES*HH];
__device__ float    g_asrc[N_NODES*HEADS];
__device__ float    g_adst[N_NODES*HEADS];

// ---------------- dtype detection + edge decode ----------------
// If edge_index is int64 (values < 2^31), every odd 32-bit word of the first
// 128 words is 0. For int32 inputs those words are random node ids.
__global__ void k_detect(const unsigned* __restrict__ w){
    if (threadIdx.x == 0){
        int all0 = 1;
        for (int i = 1; i < 128; i += 2) if (w[i] != 0u) all0 = 0;
        g_is64 = all0;
    }
}

__global__ void k_decode(const int* __restrict__ w){
    int e = blockIdx.x * blockDim.x + threadIdx.x;
    if (e >= E_TOT) return;
    if (e < N_NODES) g_deg[e] = 0;          // zero histogram on the side
    if (e < N_EDGES){
        if (g_is64){
            g_src[e] = w[2*e];
            g_dst[e] = w[2*(N_EDGES + e)];
        } else {
            g_src[e] = w[e];
            g_dst[e] = w[N_EDGES + e];
        }
    } else {
        g_src[e] = e - N_EDGES;             // self loop
        g_dst[e] = e - N_EDGES;
    }
}

__global__ void k_hist(){
    int e = blockIdx.x * blockDim.x + threadIdx.x;
    if (e >= E_TOT) return;
    atomicAdd(&g_deg[g_dst[e]], 1);
}

// single-block exclusive scan over degrees -> rowptr, cursor
__global__ void k_scan(){
    __shared__ int s[1024];
    __shared__ int carry;
    int t = threadIdx.x;
    if (t == 0) carry = 0;
    __syncthreads();
    for (int base = 0; base < N_NODES; base += 1024){
        int i = base + t;
        int v = (i < N_NODES) ? g_deg[i] : 0;
        s[t] = v;
        __syncthreads();
        for (int off = 1; off < 1024; off <<= 1){
            int add = (t >= off) ? s[t - off] : 0;
            __syncthreads();
            s[t] += add;
            __syncthreads();
        }
        int excl = s[t] - v;
        if (i < N_NODES){
            g_rowptr[i] = carry + excl;
            g_cursor[i] = carry + excl;
        }
        __syncthreads();
        if (t == 0) carry += s[1023];
        __syncthreads();
    }
    if (t == 0) g_rowptr[N_NODES] = carry;
}

__global__ void k_scatter(){
    int e = blockIdx.x * blockDim.x + threadIdx.x;
    if (e >= E_TOT) return;
    int d = g_dst[e];
    int pos = atomicAdd(&g_cursor[d], 1);
    g_csrc[pos] = g_src[e];
}

// ---------------- encoder: Y = relu(x @ W_enc + b_enc); X = Y ----------------
__global__ void k_encoder(const float* __restrict__ x,
                          const float* __restrict__ We,
                          const float* __restrict__ be){
    int nb = blockIdx.x * 8;
    int t  = threadIdx.x;
    __shared__ float xs[8][NFEAT];
    for (int r = t; r < 8*NFEAT; r += 64)
        xs[r >> 7][r & 127] = x[(nb + (r >> 7)) * NFEAT + (r & 127)];
    __syncthreads();
    float acc[8];
    float b = be[t];
#pragma unroll
    for (int m = 0; m < 8; m++) acc[m] = b;
    for (int k = 0; k < NFEAT; k++){
        float w = We[k * NHID + t];
#pragma unroll
        for (int m = 0; m < 8; m++) acc[m] = fmaf(xs[m][k], w, acc[m]);
    }
#pragma unroll
    for (int m = 0; m < 8; m++){
        float v = fmaxf(acc[m], 0.f);
        g_Y[(nb + m) * NHID + t] = v;
        g_X[(nb + m) * NHID + t] = v;
    }
}

// ---------------- per-layer projection: h = X @ W_gat, a_src, a_dst ----------------
__global__ void k_gat_proj(const float* __restrict__ Wg,
                           const float* __restrict__ atts,
                           const float* __restrict__ attd){
    int nb = blockIdx.x * 8;
    int t  = threadIdx.x;
    __shared__ float xs[8][NHID];
    __shared__ float sps[8][HH];
    __shared__ float spd[8][HH];
    for (int r = t; r < 8*NHID; r += 256)
        xs[r >> 6][r & 63] = g_X[(nb + (r >> 6)) * NHID + (r & 63)];
    __syncthreads();
    float acc[8] = {0,0,0,0,0,0,0,0};
    for (int k = 0; k < NHID; k++){
        float w = Wg[k * HH + t];
#pragma unroll
        for (int m = 0; m < 8; m++) acc[m] = fmaf(xs[m][k], w, acc[m]);
    }
    float as_ = atts[t], ad_ = attd[t];
#pragma unroll
    for (int m = 0; m < 8; m++){
        g_h[(nb + m) * HH + t] = acc[m];
        sps[m][t] = acc[m] * as_;
        spd[m][t] = acc[m] * ad_;
    }
    __syncthreads();
    int w = t >> 5, l = t & 31;
#pragma unroll
    for (int h = 0; h < HEADS; h++){
        float v1 = sps[w][h*64 + l] + sps[w][h*64 + 32 + l];
        float v2 = spd[w][h*64 + l] + spd[w][h*64 + 32 + l];
#pragma unroll
        for (int s = 16; s > 0; s >>= 1){
            v1 += __shfl_down_sync(0xffffffffu, v1, s);
            v2 += __shfl_down_sync(0xffffffffu, v2, s);
        }
        if (l == 0){
            g_asrc[(nb + w) * HEADS + h] = v1;
            g_adst[(nb + w) * HEADS + h] = v2;
        }
    }
}

// ---------------- fused per-node aggregation + softmax + GraphCON update ----------------
// one block = one destination node, 256 threads = channel (head*64+feat)
__global__ void k_node_agg(const float* __restrict__ bg){
    int n = blockIdx.x;
    int t = threadIdx.x, lane = t & 31, warp = t >> 5;
    int r0 = g_rowptr[n], r1 = g_rowptr[n+1];
    int deg = r1 - r0;

    __shared__ float s_em[HEADS];
    __shared__ float s_den[HEADS];
    __shared__ int   s_src[32];
    __shared__ float s_ex[HEADS][32];
    __shared__ float s_conv[HH];
    __shared__ float sx[NHID], sy[NHID];

    float adst_h = (warp < HEADS) ? g_adst[n * HEADS + warp] : 0.f;

    // pass A: per-head running max of a_src over incoming edges (lrelu monotone)
    if (warp < HEADS){
        float m = -1e30f;
        for (int j = lane; j < deg; j += 32){
            int s = g_csrc[r0 + j];
            m = fmaxf(m, g_asrc[s * HEADS + warp]);
        }
#pragma unroll
        for (int o = 16; o > 0; o >>= 1)
            m = fmaxf(m, __shfl_down_sync(0xffffffffu, m, o));
        if (lane == 0){
            float v = m + adst_h;
            v = (v > 0.f) ? v : 0.2f * v;
            s_em[warp] = v;
        }
    }
    __syncthreads();

    float acc = 0.f;
    float dpart = 0.f;
    int   h = t >> 6;
    for (int base = 0; base < deg; base += 32){
        int cnt = min(32, deg - base);
        if (t < cnt) s_src[t] = g_csrc[r0 + base + t];
        __syncthreads();
        if (warp < HEADS && lane < cnt){
            int s = s_src[lane];
            float v = g_asrc[s * HEADS + warp] + adst_h;
            v = (v > 0.f) ? v : 0.2f * v;
            float ex = __expf(v - s_em[warp]);
            s_ex[warp][lane] = ex;
            dpart += ex;
        }
        __syncthreads();
        for (int j = 0; j < cnt; j++)
            acc = fmaf(g_h[s_src[j] * HH + t], s_ex[h][j], acc);
        __syncthreads();
    }
    if (warp < HEADS){
#pragma unroll
        for (int o = 16; o > 0; o >>= 1)
            dpart += __shfl_down_sync(0xffffffffu, dpart, o);
        if (lane == 0) s_den[warp] = dpart;
    }
    __syncthreads();

    // conv channel value: softmax-normalized aggregate + bias, then elu
    float cv = acc / (s_den[h] + 1e-16f) + bg[t];
    cv = (cv > 0.f) ? cv : (__expf(cv) - 1.f);
    s_conv[t] = cv;
    __syncthreads();

    // GraphCON update on 64 hidden units
    float xn = 0.f, yn = 0.f;
    if (t < NHID){
        float aggv = 0.25f * (s_conv[4*t] + s_conv[4*t+1] + s_conv[4*t+2] + s_conv[4*t+3]);
        float y = g_Y[n * NHID + t];
        float x = g_X[n * NHID + t];
        yn = y + (SP1 * aggv - 2.f * SP1 * SP1 * y - SP1 * SP1 * x);
        xn = x + yn;
        sx[t] = xn * xn;
        sy[t] = yn * yn;
    }
    __syncthreads();
#pragma unroll
    for (int s = 32; s > 0; s >>= 1){
        if (t < s){ sx[t] += sx[t + s]; sy[t] += sy[t + s]; }
        __syncthreads();
    }
    if (t < NHID){
        float rx = rsqrtf(sx[0] * (1.f / NHID) + 1e-5f);
        float ry = rsqrtf(sy[0] * (1.f / NHID) + 1e-5f);
        g_X[n * NHID + t] = xn * rx;
        g_Y[n * NHID + t] = yn * ry;
    }
}

// ---------------- decoder: out = X @ W_dec + b_dec ----------------
__global__ void k_decoder(const float* __restrict__ Wd,
                          const float* __restrict__ bd,
                          float* __restrict__ out){
    int gid = blockIdx.x * blockDim.x + threadIdx.x;
    if (gid >= N_NODES * NCLASS) return;
    int n = gid >> 4, j = gid & 15;
    float acc = bd[j];
#pragma unroll
    for (int k = 0; k < NHID; k++)
        acc = fmaf(g_X[n * NHID + k], Wd[k * NCLASS + j], acc);
    out[gid] = acc;
}

extern "C" void kernel_launch(void* const* d_in, const int* in_sizes, int n_in,
                              void* d_out, int out_size){
    const float* x    = (const float*)d_in[0];
    const void*  ei   = d_in[1];
    const float* We   = (const float*)d_in[2];
    const float* be   = (const float*)d_in[3];
    const float* Wg   = (const float*)d_in[4];
    const float* atts = (const float*)d_in[5];
    const float* attd = (const float*)d_in[6];
    const float* bg   = (const float*)d_in[7];
    const float* Wd   = (const float*)d_in[8];
    const float* bd   = (const float*)d_in[9];
    float* out = (float*)d_out;

    // CSR build (edges constant across layers)
    k_detect<<<1, 32>>>((const unsigned*)ei);
    k_decode<<<(E_TOT + 255)/256, 256>>>((const int*)ei);
    k_hist<<<(E_TOT + 255)/256, 256>>>();
    k_scan<<<1, 1024>>>();
    k_scatter<<<(E_TOT + 255)/256, 256>>>();

    k_encoder<<<N_NODES/8, 64>>>(x, We, be);
    for (int l = 0; l < 3; l++){
        k_gat_proj<<<N_NODES/8, 256>>>(Wg, atts, attd);
        k_node_agg<<<N_NODES, 256>>>(bg);
    }
    k_decoder<<<(N_NODES*NCLASS + 255)/256, 256>>>(Wd, bd, out);
}

// round 4
// speedup vs baseline: 2.2980x; 1.1188x over previous
#include <cuda_runtime.h>
#include <math.h>

#define N_NODES 20000
#define N_EDGES 320000
#define E_TOT   340000   // edges + self loops
#define NFEAT   128
#define NHID    64
#define HEADS   4
#define HH      256      // HEADS*NHID
#define NCLASS  16

// softplus(1.0)
#define SP1 1.3132616875182228f

// ---------------- scratch (device globals, no allocation) ----------------
__device__ int      g_is64;
__device__ int      g_src[E_TOT];
__device__ int      g_dst[E_TOT];
__device__ int      g_deg[N_NODES];
__device__ int      g_rowptr[N_NODES + 1];
__device__ int      g_cursor[N_NODES];
__device__ int      g_csrc[E_TOT];          // CSR-by-destination source list
__device__ float    g_X[N_NODES*NHID];
__device__ float    g_Y[N_NODES*NHID];
__device__ float    g_h[N_NODES*HH];
__device__ float    g_asrc[N_NODES*HEADS];
__device__ float    g_adst[N_NODES*HEADS];

// ---------------- dtype detect + zero histogram ----------------
// If edge_index is int64 (values < 2^31), every odd 32-bit word of the first
// 128 words is 0. For int32 inputs those words are random node ids.
__global__ void k_detect(const unsigned* __restrict__ w){
    int gid = blockIdx.x * blockDim.x + threadIdx.x;
    if (gid < N_NODES) g_deg[gid] = 0;
    if (gid == 0){
        int all0 = 1;
        for (int i = 1; i < 128; i += 2) if (w[i] != 0u) all0 = 0;
        g_is64 = all0;
    }
}

// decode edges + histogram destinations in one pass
__global__ void k_decode(const int* __restrict__ w){
    int e = blockIdx.x * blockDim.x + threadIdx.x;
    if (e >= E_TOT) return;
    int s, d;
    if (e < N_EDGES){
        if (g_is64){ s = w[2*e]; d = w[2*(N_EDGES + e)]; }
        else       { s = w[e];   d = w[N_EDGES + e]; }
    } else {
        s = d = e - N_EDGES;                // self loop
    }
    g_src[e] = s;
    g_dst[e] = d;
    atomicAdd(&g_deg[d], 1);
}

// single-block, single-pass blocked exclusive scan: thread t owns 20 elements
#define SCAN_CH 20
__global__ void k_scan(){
    int t = threadIdx.x, lane = t & 31, w = t >> 5;
    int base = t * SCAN_CH;
    int v[SCAN_CH];
    int sum = 0;
#pragma unroll
    for (int i = 0; i < SCAN_CH; i++){
        int idx = base + i;
        v[i] = (idx < N_NODES) ? g_deg[idx] : 0;
        sum += v[i];
    }
    // inclusive warp scan of per-thread sums
    int s = sum;
#pragma unroll
    for (int off = 1; off < 32; off <<= 1){
        int n = __shfl_up_sync(0xffffffffu, s, off);
        if (lane >= off) s += n;
    }
    __shared__ int wtot[32];
    if (lane == 31) wtot[w] = s;
    __syncthreads();
    if (w == 0){
        int ws = wtot[lane];
#pragma unroll
        for (int off = 1; off < 32; off <<= 1){
            int n = __shfl_up_sync(0xffffffffu, ws, off);
            if (lane >= off) ws += n;
        }
        wtot[lane] = ws;      // inclusive warp totals
    }
    __syncthreads();
    int excl = (s - sum) + (w > 0 ? wtot[w - 1] : 0);
    int run = excl;
#pragma unroll
    for (int i = 0; i < SCAN_CH; i++){
        int idx = base + i;
        if (idx < N_NODES){ g_rowptr[idx] = run; g_cursor[idx] = run; }
        run += v[i];
    }
    if (t == 1023) g_rowptr[N_NODES] = run;
}

__global__ void k_scatter(){
    int e = blockIdx.x * blockDim.x + threadIdx.x;
    if (e >= E_TOT) return;
    int d = g_dst[e];
    int pos = atomicAdd(&g_cursor[d], 1);
    g_csrc[pos] = g_src[e];
}

// ---------------- encoder: Y = relu(x @ W_enc + b_enc); X = Y ----------------
// 16 nodes per block, 64 threads (thread = hidden unit)
__global__ void k_encoder(const float* __restrict__ x,
                          const float* __restrict__ We,
                          const float* __restrict__ be){
    int nb = blockIdx.x * 16;
    int t  = threadIdx.x;
    __shared__ float xs[16][NFEAT];
    for (int r = t; r < 16*NFEAT; r += 64)
        xs[r >> 7][r & 127] = x[(nb + (r >> 7)) * NFEAT + (r & 127)];
    __syncthreads();
    float acc[16];
    float b = be[t];
#pragma unroll
    for (int m = 0; m < 16; m++) acc[m] = b;
    for (int k = 0; k < NFEAT; k++){
        float w = We[k * NHID + t];
#pragma unroll
        for (int m = 0; m < 16; m++) acc[m] = fmaf(xs[m][k], w, acc[m]);
    }
#pragma unroll
    for (int m = 0; m < 16; m++){
        float v = fmaxf(acc[m], 0.f);
        g_Y[(nb + m) * NHID + t] = v;
        g_X[(nb + m) * NHID + t] = v;
    }
}

// ---------------- per-layer projection: h = X @ W_gat, a_src, a_dst ----------------
// 16 nodes per block, 256 threads (thread = output column j = head*64+f)
__global__ void k_gat_proj(const float* __restrict__ Wg,
                           const float* __restrict__ atts,
                           const float* __restrict__ attd){
    int nb = blockIdx.x * 16;
    int t  = threadIdx.x;
    __shared__ float xs[16][NHID];
    __shared__ float sps[16][HH];
    __shared__ float spd[16][HH];
    for (int r = t; r < 16*NHID; r += 256)
        xs[r >> 6][r & 63] = g_X[(nb + (r >> 6)) * NHID + (r & 63)];
    __syncthreads();
    float acc[16];
#pragma unroll
    for (int m = 0; m < 16; m++) acc[m] = 0.f;
    for (int k = 0; k < NHID; k++){
        float w = Wg[k * HH + t];
#pragma unroll
        for (int m = 0; m < 16; m++) acc[m] = fmaf(xs[m][k], w, acc[m]);
    }
    float as_ = atts[t], ad_ = attd[t];
#pragma unroll
    for (int m = 0; m < 16; m++){
        g_h[(nb + m) * HH + t] = acc[m];
        sps[m][t] = acc[m] * as_;
        spd[m][t] = acc[m] * ad_;
    }
    __syncthreads();
    // warp w reduces nodes w and w+8, all 4 heads
    int w = t >> 5, l = t & 31;
#pragma unroll
    for (int mm = 0; mm < 2; mm++){
        int m = w + mm * 8;
#pragma unroll
        for (int h = 0; h < HEADS; h++){
            float v1 = sps[m][h*64 + l] + sps[m][h*64 + 32 + l];
            float v2 = spd[m][h*64 + l] + spd[m][h*64 + 32 + l];
#pragma unroll
            for (int o = 16; o > 0; o >>= 1){
                v1 += __shfl_down_sync(0xffffffffu, v1, o);
                v2 += __shfl_down_sync(0xffffffffu, v2, o);
            }
            if (l == 0){
                g_asrc[(nb + m) * HEADS + h] = v1;
                g_adst[(nb + m) * HEADS + h] = v2;
            }
        }
    }
}

// ---------------- fused per-node aggregation + softmax + GraphCON update ----------------
// one block = one destination node, 256 threads = channel (head*64+feat)
#define WIN 128
__global__ void k_node_agg(const float* __restrict__ bg){
    int n = blockIdx.x;
    int t = threadIdx.x, lane = t & 31, warp = t >> 5;
    int r0 = g_rowptr[n], r1 = g_rowptr[n+1];
    int deg = r1 - r0;

    __shared__ float s_em[HEADS];
    __shared__ float s_den[HEADS];
    __shared__ int   s_src[WIN];
    __shared__ float s_ex[HEADS][WIN];
    __shared__ float s_conv[HH];
    __shared__ float sx[NHID], sy[NHID];

    float adst_h = (warp < HEADS) ? g_adst[n * HEADS + warp] : 0.f;

    // pass A: per-head max of a_src over incoming edges (lrelu monotone)
    if (warp < HEADS){
        float m = -1e30f;
        for (int j = lane; j < deg; j += 32)
            m = fmaxf(m, g_asrc[g_csrc[r0 + j] * HEADS + warp]);
#pragma unroll
        for (int o = 16; o > 0; o >>= 1)
            m = fmaxf(m, __shfl_down_sync(0xffffffffu, m, o));
        if (lane == 0){
            float v = m + adst_h;
            s_em[warp] = (v > 0.f) ? v : 0.2f * v;
        }
    }
    __syncthreads();

    float acc = 0.f;
    float dpart = 0.f;
    int   h = t >> 6;
    for (int base = 0; base < deg; base += WIN){
        int cnt = min(WIN, deg - base);
        for (int j = t; j < cnt; j += 256) s_src[j] = g_csrc[r0 + base + j];
        __syncthreads();
        if (warp < HEADS){
            for (int j = lane; j < cnt; j += 32){
                int s = s_src[j];
                float v = g_asrc[s * HEADS + warp] + adst_h;
                v = (v > 0.f) ? v : 0.2f * v;
                float ex = __expf(v - s_em[warp]);
                s_ex[warp][j] = ex;
                dpart += ex;
            }
        }
        __syncthreads();
        int j = 0;
        for (; j + 4 <= cnt; j += 4){
            int s0 = s_src[j],   s1 = s_src[j+1];
            int s2 = s_src[j+2], s3 = s_src[j+3];
            float e0 = s_ex[h][j],   e1 = s_ex[h][j+1];
            float e2 = s_ex[h][j+2], e3 = s_ex[h][j+3];
            acc = fmaf(g_h[s0 * HH + t], e0, acc);
            acc = fmaf(g_h[s1 * HH + t], e1, acc);
            acc = fmaf(g_h[s2 * HH + t], e2, acc);
            acc = fmaf(g_h[s3 * HH + t], e3, acc);
        }
        for (; j < cnt; j++)
            acc = fmaf(g_h[s_src[j] * HH + t], s_ex[h][j], acc);
        __syncthreads();
    }
    if (warp < HEADS){
#pragma unroll
        for (int o = 16; o > 0; o >>= 1)
            dpart += __shfl_down_sync(0xffffffffu, dpart, o);
        if (lane == 0) s_den[warp] = dpart;
    }
    __syncthreads();

    // conv channel value: softmax-normalized aggregate + bias, then elu
    float cv = acc / (s_den[h] + 1e-16f) + bg[t];
    cv = (cv > 0.f) ? cv : (__expf(cv) - 1.f);
    s_conv[t] = cv;
    __syncthreads();

    // GraphCON update on 64 hidden units
    float xn = 0.f, yn = 0.f;
    if (t < NHID){
        float aggv = 0.25f * (s_conv[4*t] + s_conv[4*t+1] + s_conv[4*t+2] + s_conv[4*t+3]);
        float y = g_Y[n * NHID + t];
        float x = g_X[n * NHID + t];
        yn = y + (SP1 * aggv - 2.f * SP1 * SP1 * y - SP1 * SP1 * x);
        xn = x + yn;
        sx[t] = xn * xn;
        sy[t] = yn * yn;
    }
    __syncthreads();
#pragma unroll
    for (int o = 32; o > 0; o >>= 1){
        if (t < o){ sx[t] += sx[t + o]; sy[t] += sy[t + o]; }
        __syncthreads();
    }
    if (t < NHID){
        float rx = rsqrtf(sx[0] * (1.f / NHID) + 1e-5f);
        float ry = rsqrtf(sy[0] * (1.f / NHID) + 1e-5f);
        g_X[n * NHID + t] = xn * rx;
        g_Y[n * NHID + t] = yn * ry;
    }
}

// ---------------- decoder: out = X @ W_dec + b_dec ----------------
__global__ void k_decoder(const float* __restrict__ Wd,
                          const float* __restrict__ bd,
                          float* __restrict__ out){
    int gid = blockIdx.x * blockDim.x + threadIdx.x;
    if (gid >= N_NODES * NCLASS) return;
    int n = gid >> 4, j = gid & 15;
    float acc = bd[j];
#pragma unroll
    for (int k = 0; k < NHID; k++)
        acc = fmaf(g_X[n * NHID + k], Wd[k * NCLASS + j], acc);
    out[gid] = acc;
}

extern "C" void kernel_launch(void* const* d_in, const int* in_sizes, int n_in,
                              void* d_out, int out_size){
    const float* x    = (const float*)d_in[0];
    const void*  ei   = d_in[1];
    const float* We   = (const float*)d_in[2];
    const float* be   = (const float*)d_in[3];
    const float* Wg   = (const float*)d_in[4];
    const float* atts = (const float*)d_in[5];
    const float* attd = (const float*)d_in[6];
    const float* bg   = (const float*)d_in[7];
    const float* Wd   = (const float*)d_in[8];
    const float* bd   = (const float*)d_in[9];
    float* out = (float*)d_out;

    // CSR build (edges constant across layers)
    k_detect<<<(N_NODES + 255)/256, 256>>>((const unsigned*)ei);
    k_decode<<<(E_TOT + 255)/256, 256>>>((const int*)ei);
    k_scan<<<1, 1024>>>();
    k_scatter<<<(E_TOT + 255)/256, 256>>>();

    k_encoder<<<N_NODES/16, 64>>>(x, We, be);
    for (int l = 0; l < 3; l++){
        k_gat_proj<<<N_NODES/16, 256>>>(Wg, atts, attd);
        k_node_agg<<<N_NODES, 256>>>(bg);
    }
    k_decoder<<<(N_NODES*NCLASS + 255)/256, 256>>>(Wd, bd, out);
}

// round 5
// speedup vs baseline: 2.4295x; 1.0572x over previous
#include <cuda_runtime.h>
#include <math.h>

#define N_NODES 20000
#define N_EDGES 320000
#define E_TOT   340000   // edges + self loops
#define NFEAT   128
#define NHID    64
#define HEADS   4
#define HH      256      // HEADS*NHID
#define NCLASS  16

// softplus(1.0)
#define SP1 1.3132616875182228f

// ---------------- scratch (device globals, no allocation) ----------------
__device__ int    g_is64;
__device__ int    g_src[E_TOT];
__device__ int    g_dst[E_TOT];
__device__ int    g_deg[N_NODES];
__device__ int    g_rowptr[N_NODES + 1];
__device__ int    g_cursor[N_NODES];
__device__ int    g_csrc[E_TOT];            // CSR-by-destination source list
__device__ int    g_cdst[E_TOT];            // destination of each CSR slot
__device__ __align__(16) float g_ex[E_TOT*HEADS];   // per-edge exp weights (CSR order)
__device__ float  g_X[N_NODES*NHID];
__device__ float  g_Y[N_NODES*NHID];
__device__ float  g_h[N_NODES*HH];
__device__ __align__(16) float g_asrc[N_NODES*HEADS];
__device__ __align__(16) float g_adst[N_NODES*HEADS];

// ---------------- dtype detect + zero histogram ----------------
__global__ void k_detect(const unsigned* __restrict__ w){
    int gid = blockIdx.x * blockDim.x + threadIdx.x;
    if (gid < N_NODES) g_deg[gid] = 0;
    if (gid == 0){
        int all0 = 1;
        for (int i = 1; i < 128; i += 2) if (w[i] != 0u) all0 = 0;
        g_is64 = all0;
    }
}

// decode edges + histogram destinations in one pass
__global__ void k_decode(const int* __restrict__ w){
    int e = blockIdx.x * blockDim.x + threadIdx.x;
    if (e >= E_TOT) return;
    int s, d;
    if (e < N_EDGES){
        if (g_is64){ s = w[2*e]; d = w[2*(N_EDGES + e)]; }
        else       { s = w[e];   d = w[N_EDGES + e]; }
    } else {
        s = d = e - N_EDGES;                // self loop
    }
    g_src[e] = s;
    g_dst[e] = d;
    atomicAdd(&g_deg[d], 1);
}

// single-block, single-pass blocked exclusive scan: thread t owns 20 elements
#define SCAN_CH 20
__global__ void k_scan(){
    int t = threadIdx.x, lane = t & 31, w = t >> 5;
    int base = t * SCAN_CH;
    int v[SCAN_CH];
    int sum = 0;
#pragma unroll
    for (int i = 0; i < SCAN_CH; i++){
        int idx = base + i;
        v[i] = (idx < N_NODES) ? g_deg[idx] : 0;
        sum += v[i];
    }
    int s = sum;
#pragma unroll
    for (int off = 1; off < 32; off <<= 1){
        int n = __shfl_up_sync(0xffffffffu, s, off);
        if (lane >= off) s += n;
    }
    __shared__ int wtot[32];
    if (lane == 31) wtot[w] = s;
    __syncthreads();
    if (w == 0){
        int ws = wtot[lane];
#pragma unroll
        for (int off = 1; off < 32; off <<= 1){
            int n = __shfl_up_sync(0xffffffffu, ws, off);
            if (lane >= off) ws += n;
        }
        wtot[lane] = ws;
    }
    __syncthreads();
    int excl = (s - sum) + (w > 0 ? wtot[w - 1] : 0);
    int run = excl;
#pragma unroll
    for (int i = 0; i < SCAN_CH; i++){
        int idx = base + i;
        if (idx < N_NODES){ g_rowptr[idx] = run; g_cursor[idx] = run; }
        run += v[i];
    }
    if (t == 1023) g_rowptr[N_NODES] = run;
}

__global__ void k_scatter(){
    int e = blockIdx.x * blockDim.x + threadIdx.x;
    if (e >= E_TOT) return;
    int d = g_dst[e];
    int pos = atomicAdd(&g_cursor[d], 1);
    g_csrc[pos] = g_src[e];
    g_cdst[pos] = d;
}

// ---------------- encoder: Y = relu(x @ W_enc + b_enc); X = Y ----------------
__global__ void k_encoder(const float* __restrict__ x,
                          const float* __restrict__ We,
                          const float* __restrict__ be){
    int nb = blockIdx.x * 16;
    int t  = threadIdx.x;
    __shared__ float xs[16][NFEAT];
    for (int r = t; r < 16*NFEAT; r += 64)
        xs[r >> 7][r & 127] = x[(nb + (r >> 7)) * NFEAT + (r & 127)];
    __syncthreads();
    float acc[16];
    float b = be[t];
#pragma unroll
    for (int m = 0; m < 16; m++) acc[m] = b;
    for (int k = 0; k < NFEAT; k++){
        float w = We[k * NHID + t];
#pragma unroll
        for (int m = 0; m < 16; m++) acc[m] = fmaf(xs[m][k], w, acc[m]);
    }
#pragma unroll
    for (int m = 0; m < 16; m++){
        float v = fmaxf(acc[m], 0.f);
        g_Y[(nb + m) * NHID + t] = v;
        g_X[(nb + m) * NHID + t] = v;
    }
}

// ---------------- per-layer projection: h = X @ W_gat, a_src, a_dst ----------------
__global__ void k_gat_proj(const float* __restrict__ Wg,
                           const float* __restrict__ atts,
                           const float* __restrict__ attd){
    int nb = blockIdx.x * 16;
    int t  = threadIdx.x;
    __shared__ float xs[16][NHID];
    __shared__ float sps[16][HH];
    __shared__ float spd[16][HH];
    for (int r = t; r < 16*NHID; r += 256)
        xs[r >> 6][r & 63] = g_X[(nb + (r >> 6)) * NHID + (r & 63)];
    __syncthreads();
    float acc[16];
#pragma unroll
    for (int m = 0; m < 16; m++) acc[m] = 0.f;
    for (int k = 0; k < NHID; k++){
        float w = Wg[k * HH + t];
#pragma unroll
        for (int m = 0; m < 16; m++) acc[m] = fmaf(xs[m][k], w, acc[m]);
    }
    float as_ = atts[t], ad_ = attd[t];
#pragma unroll
    for (int m = 0; m < 16; m++){
        g_h[(nb + m) * HH + t] = acc[m];
        sps[m][t] = acc[m] * as_;
        spd[m][t] = acc[m] * ad_;
    }
    __syncthreads();
    int w = t >> 5, l = t & 31;
#pragma unroll
    for (int mm = 0; mm < 2; mm++){
        int m = w + mm * 8;
#pragma unroll
        for (int h = 0; h < HEADS; h++){
            float v1 = sps[m][h*64 + l] + sps[m][h*64 + 32 + l];
            float v2 = spd[m][h*64 + l] + spd[m][h*64 + 32 + l];
#pragma unroll
            for (int o = 16; o > 0; o >>= 1){
                v1 += __shfl_down_sync(0xffffffffu, v1, o);
                v2 += __shfl_down_sync(0xffffffffu, v2, o);
            }
            if (l == 0){
                g_asrc[(nb + m) * HEADS + h] = v1;
                g_adst[(nb + m) * HEADS + h] = v2;
            }
        }
    }
}

// ---------------- edge-parallel attention weights (CSR order, coalesced) ----------------
// softmax without max-subtraction: ratios identical, |e| is small so exp is safe
__global__ void k_edge_w(){
    int p = blockIdx.x * blockDim.x + threadIdx.x;
    if (p >= E_TOT) return;
    int s = g_csrc[p], d = g_cdst[p];
    float4 a = *((const float4*)g_asrc + s);
    float4 b = *((const float4*)g_adst + d);
    float4 ex;
    float v;
    v = a.x + b.x; v = (v > 0.f) ? v : 0.2f * v; ex.x = __expf(v);
    v = a.y + b.y; v = (v > 0.f) ? v : 0.2f * v; ex.y = __expf(v);
    v = a.z + b.z; v = (v > 0.f) ? v : 0.2f * v; ex.z = __expf(v);
    v = a.w + b.w; v = (v > 0.f) ? v : 0.2f * v; ex.w = __expf(v);
    ((float4*)g_ex)[p] = ex;
}

// ---------------- fused per-node gather + softmax-normalize + GraphCON update ----------------
// one block = one destination node, 256 threads = channel (head*64+feat)
#define WIN 128
__global__ void k_node_agg(const float* __restrict__ bg){
    int n = blockIdx.x;
    int t = threadIdx.x, lane = t & 31, warp = t >> 5;
    int r0 = g_rowptr[n], r1 = g_rowptr[n+1];
    int deg = r1 - r0;

    __shared__ float s_den[HEADS];
    __shared__ int   s_src[WIN];
    __shared__ float s_ex[HEADS][WIN];
    __shared__ float s_conv[HH];
    __shared__ float sx[NHID], sy[NHID];

    float acc = 0.f;
    float dpart = 0.f;
    int   h = t >> 6;
    for (int base = 0; base < deg; base += WIN){
        int cnt = min(WIN, deg - base);
        for (int j = t; j < cnt; j += 256){
            s_src[j] = g_csrc[r0 + base + j];
            float4 e4 = ((const float4*)g_ex)[r0 + base + j];
            s_ex[0][j] = e4.x; s_ex[1][j] = e4.y;
            s_ex[2][j] = e4.z; s_ex[3][j] = e4.w;
        }
        __syncthreads();
        if (warp < HEADS)
            for (int j = lane; j < cnt; j += 32) dpart += s_ex[warp][j];
        int j = 0;
        for (; j + 4 <= cnt; j += 4){
            int s0 = s_src[j],   s1 = s_src[j+1];
            int s2 = s_src[j+2], s3 = s_src[j+3];
            float e0 = s_ex[h][j],   e1 = s_ex[h][j+1];
            float e2 = s_ex[h][j+2], e3 = s_ex[h][j+3];
            acc = fmaf(g_h[s0 * HH + t], e0, acc);
            acc = fmaf(g_h[s1 * HH + t], e1, acc);
            acc = fmaf(g_h[s2 * HH + t], e2, acc);
            acc = fmaf(g_h[s3 * HH + t], e3, acc);
        }
        for (; j < cnt; j++)
            acc = fmaf(g_h[s_src[j] * HH + t], s_ex[h][j], acc);
        __syncthreads();
    }
    if (warp < HEADS){
#pragma unroll
        for (int o = 16; o > 0; o >>= 1)
            dpart += __shfl_down_sync(0xffffffffu, dpart, o);
        if (lane == 0) s_den[warp] = dpart;
    }
    __syncthreads();

    // conv channel value: softmax-normalized aggregate + bias, then elu
    float cv = acc / (s_den[h] + 1e-16f) + bg[t];
    cv = (cv > 0.f) ? cv : (__expf(cv) - 1.f);
    s_conv[t] = cv;
    __syncthreads();

    // GraphCON update on 64 hidden units
    float xn = 0.f, yn = 0.f;
    if (t < NHID){
        float aggv = 0.25f * (s_conv[4*t] + s_conv[4*t+1] + s_conv[4*t+2] + s_conv[4*t+3]);
        float y = g_Y[n * NHID + t];
        float x = g_X[n * NHID + t];
        yn = y + (SP1 * aggv - 2.f * SP1 * SP1 * y - SP1 * SP1 * x);
        xn = x + yn;
        sx[t] = xn * xn;
        sy[t] = yn * yn;
    }
    __syncthreads();
#pragma unroll
    for (int o = 32; o > 0; o >>= 1){
        if (t < o){ sx[t] += sx[t + o]; sy[t] += sy[t + o]; }
        __syncthreads();
    }
    if (t < NHID){
        float rx = rsqrtf(sx[0] * (1.f / NHID) + 1e-5f);
        float ry = rsqrtf(sy[0] * (1.f / NHID) + 1e-5f);
        g_X[n * NHID + t] = xn * rx;
        g_Y[n * NHID + t] = yn * ry;
    }
}

// ---------------- decoder: out = X @ W_dec + b_dec ----------------
__global__ void k_decoder(const float* __restrict__ Wd,
                          const float* __restrict__ bd,
                          float* __restrict__ out){
    int gid = blockIdx.x * blockDim.x + threadIdx.x;
    if (gid >= N_NODES * NCLASS) return;
    int n = gid >> 4, j = gid & 15;
    float acc = bd[j];
#pragma unroll
    for (int k = 0; k < NHID; k++)
        acc = fmaf(g_X[n * NHID + k], Wd[k * NCLASS + j], acc);
    out[gid] = acc;
}

extern "C" void kernel_launch(void* const* d_in, const int* in_sizes, int n_in,
                              void* d_out, int out_size){
    const float* x    = (const float*)d_in[0];
    const void*  ei   = d_in[1];
    const float* We   = (const float*)d_in[2];
    const float* be   = (const float*)d_in[3];
    const float* Wg   = (const float*)d_in[4];
    const float* atts = (const float*)d_in[5];
    const float* attd = (const float*)d_in[6];
    const float* bg   = (const float*)d_in[7];
    const float* Wd   = (const float*)d_in[8];
    const float* bd   = (const float*)d_in[9];
    float* out = (float*)d_out;

    // CSR build (edges constant across layers)
    k_detect<<<(N_NODES + 255)/256, 256>>>((const unsigned*)ei);
    k_decode<<<(E_TOT + 255)/256, 256>>>((const int*)ei);
    k_scan<<<1, 1024>>>();
    k_scatter<<<(E_TOT + 255)/256, 256>>>();

    k_encoder<<<N_NODES/16, 64>>>(x, We, be);
    for (int l = 0; l < 3; l++){
        k_gat_proj<<<N_NODES/16, 256>>>(Wg, atts, attd);
        k_edge_w<<<(E_TOT + 255)/256, 256>>>();
        k_node_agg<<<N_NODES, 256>>>(bg);
    }
    k_decoder<<<(N_NODES*NCLASS + 255)/256, 256>>>(Wd, bd, out);
}

// round 6
// speedup vs baseline: 2.6536x; 1.0922x over previous
#include <cuda_runtime.h>
#include <math.h>

#define N_NODES 20000
#define N_EDGES 320000
#define E_TOT   340000   // edges + self loops
#define NFEAT   128
#define NHID    64
#define HEADS   4
#define HH      256      // HEADS*NHID
#define NCLASS  16

// softplus(1.0)
#define SP1 1.3132616875182228f

// ---------------- scratch (device globals, no allocation) ----------------
__device__ int    g_is64;
__device__ int    g_src[E_TOT];
__device__ int    g_dst[E_TOT];
__device__ int    g_deg[N_NODES];
__device__ int    g_rowptr[N_NODES + 1];
__device__ int    g_cursor[N_NODES];
__device__ int    g_csrc[E_TOT];            // CSR-by-destination source list
__device__ float  g_X[N_NODES*NHID];
__device__ float  g_Y[N_NODES*NHID];
__device__ float  g_h[N_NODES*HH];
__device__ __align__(16) float g_asrc[N_NODES*HEADS];
__device__ __align__(16) float g_adst[N_NODES*HEADS];

// ---------------- dtype detect + zero histogram ----------------
__global__ void k_detect(const unsigned* __restrict__ w){
    int gid = blockIdx.x * blockDim.x + threadIdx.x;
    if (gid < N_NODES) g_deg[gid] = 0;
    if (gid == 0){
        int all0 = 1;
        for (int i = 1; i < 128; i += 2) if (w[i] != 0u) all0 = 0;
        g_is64 = all0;
    }
}

// decode edges + histogram destinations in one pass
__global__ void k_decode(const int* __restrict__ w){
    int e = blockIdx.x * blockDim.x + threadIdx.x;
    if (e >= E_TOT) return;
    int s, d;
    if (e < N_EDGES){
        if (g_is64){ s = w[2*e]; d = w[2*(N_EDGES + e)]; }
        else       { s = w[e];   d = w[N_EDGES + e]; }
    } else {
        s = d = e - N_EDGES;                // self loop
    }
    g_src[e] = s;
    g_dst[e] = d;
    atomicAdd(&g_deg[d], 1);
}

// single-block, single-pass blocked exclusive scan: thread t owns 20 elements
#define SCAN_CH 20
__global__ void k_scan(){
    int t = threadIdx.x, lane = t & 31, w = t >> 5;
    int base = t * SCAN_CH;
    int v[SCAN_CH];
    int sum = 0;
#pragma unroll
    for (int i = 0; i < SCAN_CH; i++){
        int idx = base + i;
        v[i] = (idx < N_NODES) ? g_deg[idx] : 0;
        sum += v[i];
    }
    int s = sum;
#pragma unroll
    for (int off = 1; off < 32; off <<= 1){
        int n = __shfl_up_sync(0xffffffffu, s, off);
        if (lane >= off) s += n;
    }
    __shared__ int wtot[32];
    if (lane == 31) wtot[w] = s;
    __syncthreads();
    if (w == 0){
        int ws = wtot[lane];
#pragma unroll
        for (int off = 1; off < 32; off <<= 1){
            int n = __shfl_up_sync(0xffffffffu, ws, off);
            if (lane >= off) ws += n;
        }
        wtot[lane] = ws;
    }
    __syncthreads();
    int excl = (s - sum) + (w > 0 ? wtot[w - 1] : 0);
    int run = excl;
#pragma unroll
    for (int i = 0; i < SCAN_CH; i++){
        int idx = base + i;
        if (idx < N_NODES){ g_rowptr[idx] = run; g_cursor[idx] = run; }
        run += v[i];
    }
    if (t == 1023) g_rowptr[N_NODES] = run;
}

__global__ void k_scatter(){
    int e = blockIdx.x * blockDim.x + threadIdx.x;
    if (e >= E_TOT) return;
    int d = g_dst[e];
    int pos = atomicAdd(&g_cursor[d], 1);
    g_csrc[pos] = g_src[e];
}

// ---------------- encoder: Y = relu(x @ W_enc + b_enc); X = Y ----------------
__global__ void k_encoder(const float* __restrict__ x,
                          const float* __restrict__ We,
                          const float* __restrict__ be){
    int nb = blockIdx.x * 16;
    int t  = threadIdx.x;
    __shared__ float xs[16][NFEAT];
    for (int r = t; r < 16*NFEAT; r += 64)
        xs[r >> 7][r & 127] = x[(nb + (r >> 7)) * NFEAT + (r & 127)];
    __syncthreads();
    float acc[16];
    float b = be[t];
#pragma unroll
    for (int m = 0; m < 16; m++) acc[m] = b;
    for (int k = 0; k < NFEAT; k++){
        float w = We[k * NHID + t];
#pragma unroll
        for (int m = 0; m < 16; m++) acc[m] = fmaf(xs[m][k], w, acc[m]);
    }
#pragma unroll
    for (int m = 0; m < 16; m++){
        float v = fmaxf(acc[m], 0.f);
        g_Y[(nb + m) * NHID + t] = v;
        g_X[(nb + m) * NHID + t] = v;
    }
}

// ---------------- per-layer projection: h = X @ W_gat, a_src, a_dst ----------------
__global__ void k_gat_proj(const float* __restrict__ Wg,
                           const float* __restrict__ atts,
                           const float* __restrict__ attd){
    int nb = blockIdx.x * 16;
    int t  = threadIdx.x;
    __shared__ float xs[16][NHID];
    __shared__ float sps[16][HH];
    __shared__ float spd[16][HH];
    for (int r = t; r < 16*NHID; r += 256)
        xs[r >> 6][r & 63] = g_X[(nb + (r >> 6)) * NHID + (r & 63)];
    __syncthreads();
    float acc[16];
#pragma unroll
    for (int m = 0; m < 16; m++) acc[m] = 0.f;
    for (int k = 0; k < NHID; k++){
        float w = Wg[k * HH + t];
#pragma unroll
        for (int m = 0; m < 16; m++) acc[m] = fmaf(xs[m][k], w, acc[m]);
    }
    float as_ = atts[t], ad_ = attd[t];
#pragma unroll
    for (int m = 0; m < 16; m++){
        g_h[(nb + m) * HH + t] = acc[m];
        sps[m][t] = acc[m] * as_;
        spd[m][t] = acc[m] * ad_;
    }
    __syncthreads();
    int w = t >> 5, l = t & 31;
#pragma unroll
    for (int mm = 0; mm < 2; mm++){
        int m = w + mm * 8;
#pragma unroll
        for (int h = 0; h < HEADS; h++){
            float v1 = sps[m][h*64 + l] + sps[m][h*64 + 32 + l];
            float v2 = spd[m][h*64 + l] + spd[m][h*64 + 32 + l];
#pragma unroll
            for (int o = 16; o > 0; o >>= 1){
                v1 += __shfl_down_sync(0xffffffffu, v1, o);
                v2 += __shfl_down_sync(0xffffffffu, v2, o);
            }
            if (l == 0){
                g_asrc[(nb + m) * HEADS + h] = v1;
                g_adst[(nb + m) * HEADS + h] = v2;
            }
        }
    }
}

// ---------------- fused per-node: attention weights + gather + normalize + GraphCON ----------------
// one block = one destination node, 256 threads = channel (head*64+feat)
// softmax without max-subtraction: ratios identical, |e| is small so exp is safe
#define WIN 128
__global__ void k_node_agg(const float* __restrict__ bg){
    int n = blockIdx.x;
    int t = threadIdx.x, lane = t & 31, warp = t >> 5;
    int r0 = g_rowptr[n], deg = g_rowptr[n+1] - r0;

    __shared__ float s_den[HEADS];
    __shared__ int   s_src[WIN];
    __shared__ float s_ex[HEADS][WIN];
    __shared__ float s_conv[HH];
    __shared__ float s_px[2], s_py[2];

    // prefetches (hide epilogue latency behind the gather phase)
    float bgv = bg[t];
    float xv = 0.f, yv = 0.f;
    if (t < NHID){ xv = g_X[n * NHID + t]; yv = g_Y[n * NHID + t]; }
    float4 bdst = ((const float4*)g_adst)[n];

    float acc = 0.f;
    float dpart = 0.f;
    int   h = t >> 6;
    for (int base = 0; base < deg; base += WIN){
        int cnt = min(WIN, deg - base);
        for (int j = t; j < cnt; j += 256){
            int s = g_csrc[r0 + base + j];
            s_src[j] = s;
            float4 a = ((const float4*)g_asrc)[s];
            float v;
            v = a.x + bdst.x; v = (v > 0.f) ? v : 0.2f * v; s_ex[0][j] = __expf(v);
            v = a.y + bdst.y; v = (v > 0.f) ? v : 0.2f * v; s_ex[1][j] = __expf(v);
            v = a.z + bdst.z; v = (v > 0.f) ? v : 0.2f * v; s_ex[2][j] = __expf(v);
            v = a.w + bdst.w; v = (v > 0.f) ? v : 0.2f * v; s_ex[3][j] = __expf(v);
        }
        __syncthreads();
        if (warp < HEADS)
            for (int j = lane; j < cnt; j += 32) dpart += s_ex[warp][j];
        int j = 0;
        for (; j + 8 <= cnt; j += 8){
            float a0 = g_h[s_src[j  ] * HH + t];
            float a1 = g_h[s_src[j+1] * HH + t];
            float a2 = g_h[s_src[j+2] * HH + t];
            float a3 = g_h[s_src[j+3] * HH + t];
            float a4 = g_h[s_src[j+4] * HH + t];
            float a5 = g_h[s_src[j+5] * HH + t];
            float a6 = g_h[s_src[j+6] * HH + t];
            float a7 = g_h[s_src[j+7] * HH + t];
            acc = fmaf(a0, s_ex[h][j  ], acc);
            acc = fmaf(a1, s_ex[h][j+1], acc);
            acc = fmaf(a2, s_ex[h][j+2], acc);
            acc = fmaf(a3, s_ex[h][j+3], acc);
            acc = fmaf(a4, s_ex[h][j+4], acc);
            acc = fmaf(a5, s_ex[h][j+5], acc);
            acc = fmaf(a6, s_ex[h][j+6], acc);
            acc = fmaf(a7, s_ex[h][j+7], acc);
        }
        for (; j < cnt; j++)
            acc = fmaf(g_h[s_src[j] * HH + t], s_ex[h][j], acc);
        __syncthreads();
    }
    if (warp < HEADS){
#pragma unroll
        for (int o = 16; o > 0; o >>= 1)
            dpart += __shfl_down_sync(0xffffffffu, dpart, o);
        if (lane == 0) s_den[warp] = dpart;
    }
    __syncthreads();

    // conv channel value: softmax-normalized aggregate + bias, then elu
    float cv = acc / (s_den[h] + 1e-16f) + bgv;
    cv = (cv > 0.f) ? cv : (__expf(cv) - 1.f);
    s_conv[t] = cv;
    __syncthreads();

    // GraphCON update on 64 hidden units + shuffle-based rms norms
    float xn = 0.f, yn = 0.f;
    if (t < NHID){
        float aggv = 0.25f * (s_conv[4*t] + s_conv[4*t+1] + s_conv[4*t+2] + s_conv[4*t+3]);
        yn = yv + (SP1 * aggv - 2.f * SP1 * SP1 * yv - SP1 * SP1 * xv);
        xn = xv + yn;
        float px = xn * xn, py = yn * yn;
#pragma unroll
        for (int o = 16; o > 0; o >>= 1){
            px += __shfl_down_sync(0xffffffffu, px, o);
            py += __shfl_down_sync(0xffffffffu, py, o);
        }
        if (lane == 0){ s_px[warp] = px; s_py[warp] = py; }
    }
    __syncthreads();
    if (t < NHID){
        float rx = rsqrtf((s_px[0] + s_px[1]) * (1.f / NHID) + 1e-5f);
        float ry = rsqrtf((s_py[0] + s_py[1]) * (1.f / NHID) + 1e-5f);
        g_X[n * NHID + t] = xn * rx;
        g_Y[n * NHID + t] = yn * ry;
    }
}

// ---------------- decoder: out = X @ W_dec + b_dec ----------------
__global__ void k_decoder(const float* __restrict__ Wd,
                          const float* __restrict__ bd,
                          float* __restrict__ out){
    int gid = blockIdx.x * blockDim.x + threadIdx.x;
    if (gid >= N_NODES * NCLASS) return;
    int n = gid >> 4, j = gid & 15;
    float acc = bd[j];
#pragma unroll
    for (int k = 0; k < NHID; k++)
        acc = fmaf(g_X[n * NHID + k], Wd[k * NCLASS + j], acc);
    out[gid] = acc;
}

extern "C" void kernel_launch(void* const* d_in, const int* in_sizes, int n_in,
                              void* d_out, int out_size){
    const float* x    = (const float*)d_in[0];
    const void*  ei   = d_in[1];
    const float* We   = (const float*)d_in[2];
    const float* be   = (const float*)d_in[3];
    const float* Wg   = (const float*)d_in[4];
    const float* atts = (const float*)d_in[5];
    const float* attd = (const float*)d_in[6];
    const float* bg   = (const float*)d_in[7];
    const float* Wd   = (const float*)d_in[8];
    const float* bd   = (const float*)d_in[9];
    float* out = (float*)d_out;

    // CSR build (edges constant across layers)
    k_detect<<<(N_NODES + 255)/256, 256>>>((const unsigned*)ei);
    k_decode<<<(E_TOT + 255)/256, 256>>>((const int*)ei);
    k_scan<<<1, 1024>>>();
    k_scatter<<<(E_TOT + 255)/256, 256>>>();

    k_encoder<<<N_NODES/16, 64>>>(x, We, be);
    for (int l = 0; l < 3; l++){
        k_gat_proj<<<N_NODES/16, 256>>>(Wg, atts, attd);
        k_node_agg<<<N_NODES, 256>>>(bg);
    }
    k_decoder<<<(N_NODES*NCLASS + 255)/256, 256>>>(Wd, bd, out);
}

// round 7
// speedup vs baseline: 3.3561x; 1.2648x over previous
#include <cuda_runtime.h>
#include <math.h>

#define N_NODES 20000
#define N_EDGES 320000
#define E_TOT   340000   // edges + self loops
#define NFEAT   128
#define NHID    64
#define HEADS   4
#define HH      256      // HEADS*NHID
#define NCLASS  16

// softplus(1.0)
#define SP1 1.3132616875182228f

// ---------------- scratch (device globals, no allocation) ----------------
__device__ int    g_is64;
__device__ int    g_deg[N_NODES];
__device__ int    g_rowptr[N_NODES + 1];
__device__ int    g_cursor[N_NODES];
__device__ int    g_csrc[E_TOT];            // CSR-by-destination source list
__device__ float  g_watt[NHID*8];           // folded attention weights (4 src, 4 dst cols)
__device__ __align__(16) float g_X[N_NODES*NHID];
__device__ __align__(16) float g_Y[N_NODES*NHID];
__device__ __align__(16) float g_h[N_NODES*HH];
__device__ __align__(16) float g_asrc[N_NODES*HEADS];
__device__ __align__(16) float g_adst[N_NODES*HEADS];

// decode one edge's (src,dst) from raw edge_index (int32 or int64)
__device__ __forceinline__ void edge_sd(const int* __restrict__ w, int e, int& s, int& d){
    if (e < N_EDGES){
        if (g_is64){ s = w[2*e]; d = w[2*(N_EDGES + e)]; }
        else       { s = w[e];   d = w[N_EDGES + e]; }
    } else {
        s = d = e - N_EDGES;                // self loop
    }
}

// ---------------- dtype detect + zero histogram ----------------
__global__ void k_detect(const unsigned* __restrict__ w){
    int gid = blockIdx.x * blockDim.x + threadIdx.x;
    if (gid < N_NODES) g_deg[gid] = 0;
    if (gid == 0){
        int all0 = 1;
        for (int i = 1; i < 128; i += 2) if (w[i] != 0u) all0 = 0;
        g_is64 = all0;
    }
}

__global__ void k_hist(const int* __restrict__ w){
    int e = blockIdx.x * blockDim.x + threadIdx.x;
    if (e >= E_TOT) return;
    int s, d; edge_sd(w, e, s, d);
    atomicAdd(&g_deg[d], 1);
}

// single-block, single-pass blocked exclusive scan: thread t owns 20 elements
#define SCAN_CH 20
__global__ void k_scan(){
    int t = threadIdx.x, lane = t & 31, w = t >> 5;
    int base = t * SCAN_CH;
    int v[SCAN_CH];
    int sum = 0;
#pragma unroll
    for (int i = 0; i < SCAN_CH; i++){
        int idx = base + i;
        v[i] = (idx < N_NODES) ? g_deg[idx] : 0;
        sum += v[i];
    }
    int s = sum;
#pragma unroll
    for (int off = 1; off < 32; off <<= 1){
        int n = __shfl_up_sync(0xffffffffu, s, off);
        if (lane >= off) s += n;
    }
    __shared__ int wtot[32];
    if (lane == 31) wtot[w] = s;
    __syncthreads();
    if (w == 0){
        int ws = wtot[lane];
#pragma unroll
        for (int off = 1; off < 32; off <<= 1){
            int n = __shfl_up_sync(0xffffffffu, ws, off);
            if (lane >= off) ws += n;
        }
        wtot[lane] = ws;
    }
    __syncthreads();
    int excl = (s - sum) + (w > 0 ? wtot[w - 1] : 0);
    int run = excl;
#pragma unroll
    for (int i = 0; i < SCAN_CH; i++){
        int idx = base + i;
        if (idx < N_NODES){ g_rowptr[idx] = run; g_cursor[idx] = run; }
        run += v[i];
    }
    if (t == 1023) g_rowptr[N_NODES] = run;
}

__global__ void k_scatter(const int* __restrict__ w){
    int e = blockIdx.x * blockDim.x + threadIdx.x;
    if (e >= E_TOT) return;
    int s, d; edge_sd(w, e, s, d);
    int pos = atomicAdd(&g_cursor[d], 1);
    g_csrc[pos] = s;
}

// ---------------- fold attention vectors through W_gat: w_att = Wg @ [atts|attd] ----------------
// 512 threads, 1 block: thread = (k, o); o<4 -> src head o, o>=4 -> dst head o-4
__global__ void k_prew(const float* __restrict__ Wg,
                       const float* __restrict__ atts,
                       const float* __restrict__ attd){
    int t = threadIdx.x;
    int k = t >> 3, o = t & 7;
    const float* av = (o < 4) ? (atts + (o & 3) * NHID) : (attd + (o & 3) * NHID);
    const float* wr = Wg + k * HH + (o & 3) * NHID;
    float a = 0.f;
#pragma unroll 8
    for (int f = 0; f < NHID; f++) a = fmaf(wr[f], av[f], a);
    g_watt[k * 8 + o] = a;
}

// ---------------- encoder: Y = relu(x @ W_enc + b_enc); X = Y ----------------
// 16 nodes per block, 64 threads (thread = hidden unit), float4 k-loop
__global__ void k_encoder(const float* __restrict__ x,
                          const float* __restrict__ We,
                          const float* __restrict__ be){
    int nb = blockIdx.x * 16;
    int t  = threadIdx.x;
    __shared__ float4 xs4[16][NFEAT/4];
    for (int r = t; r < 16 * (NFEAT/4); r += 64)
        xs4[r >> 5][r & 31] = ((const float4*)x)[(nb + (r >> 5)) * (NFEAT/4) + (r & 31)];
    __syncthreads();
    float acc[16];
    float b = be[t];
#pragma unroll
    for (int m = 0; m < 16; m++) acc[m] = b;
    for (int k4 = 0; k4 < NFEAT/4; k4++){
        float w0 = We[(4*k4+0) * NHID + t];
        float w1 = We[(4*k4+1) * NHID + t];
        float w2 = We[(4*k4+2) * NHID + t];
        float w3 = We[(4*k4+3) * NHID + t];
#pragma unroll
        for (int m = 0; m < 16; m++){
            float4 xv = xs4[m][k4];
            acc[m] = fmaf(xv.x, w0, acc[m]);
            acc[m] = fmaf(xv.y, w1, acc[m]);
            acc[m] = fmaf(xv.z, w2, acc[m]);
            acc[m] = fmaf(xv.w, w3, acc[m]);
        }
    }
#pragma unroll
    for (int m = 0; m < 16; m++){
        float v = fmaxf(acc[m], 0.f);
        g_Y[(nb + m) * NHID + t] = v;
        g_X[(nb + m) * NHID + t] = v;
    }
}

// ---------------- per-layer projection: h = X @ W_gat (+ folded a_src/a_dst) ----------------
// 32 nodes per block, 256 threads (thread = output column), float4 k-loop
__global__ void k_gat_proj(const float* __restrict__ Wg){
    int nb = blockIdx.x * 32;
    int t  = threadIdx.x;
    __shared__ float4 xs4[32][NHID/4];   // 8KB
    __shared__ float  watt[NHID*8];      // 2KB
    for (int r = t; r < 32 * (NHID/4); r += 256)
        xs4[r >> 4][r & 15] = ((const float4*)g_X)[(nb + (r >> 4)) * (NHID/4) + (r & 15)];
    for (int r = t; r < NHID*8; r += 256) watt[r] = g_watt[r];
    __syncthreads();
    float acc[32];
#pragma unroll
    for (int m = 0; m < 32; m++) acc[m] = 0.f;
    for (int k4 = 0; k4 < NHID/4; k4++){
        float w0 = Wg[(4*k4+0) * HH + t];
        float w1 = Wg[(4*k4+1) * HH + t];
        float w2 = Wg[(4*k4+2) * HH + t];
        float w3 = Wg[(4*k4+3) * HH + t];
#pragma unroll
        for (int m = 0; m < 32; m++){
            float4 xv = xs4[m][k4];
            acc[m] = fmaf(xv.x, w0, acc[m]);
            acc[m] = fmaf(xv.y, w1, acc[m]);
            acc[m] = fmaf(xv.z, w2, acc[m]);
            acc[m] = fmaf(xv.w, w3, acc[m]);
        }
    }
#pragma unroll
    for (int m = 0; m < 32; m++) g_h[(nb + m) * HH + t] = acc[m];

    // attention scores: 256 threads = 32 nodes x 8 outputs
    int m = t >> 3, o = t & 7;
    const float* xr = (const float*)&xs4[m][0];
    float a = 0.f;
#pragma unroll 8
    for (int k = 0; k < NHID; k++) a = fmaf(xr[k], watt[k * 8 + o], a);
    if (o < 4) g_asrc[(nb + m) * HEADS + o] = a;
    else       g_adst[(nb + m) * HEADS + (o - 4)] = a;
}

// ---------------- fused per-node: attention weights + gather + normalize + GraphCON ----------------
// one block = one destination node, 64 threads; thread t owns channels 4t..4t+3
// (same head t>>4, and exactly hidden unit t's mean group)
// softmax without max-subtraction: ratios identical, |e| is small so exp is safe
#define AWIN 64
__global__ void k_node_agg(const float* __restrict__ bg){
    int n = blockIdx.x;
    int t = threadIdx.x;                 // 0..63
    int hh = t >> 4;                     // head of this thread's channels
    int r0 = g_rowptr[n], deg = g_rowptr[n+1] - r0;

    __shared__ int   s_src[AWIN];
    __shared__ float s_ex[HEADS][AWIN];
    __shared__ float s_den[HEADS];
    __shared__ float s_px[2], s_py[2];

    // prefetch epilogue operands (hide behind gather)
    float  xv  = g_X[n * NHID + t];
    float  yv  = g_Y[n * NHID + t];
    float4 bgv = ((const float4*)bg)[t];
    float4 bdst = ((const float4*)g_adst)[n];

    const float4* gh4 = (const float4*)g_h;
    float4 acc = make_float4(0.f, 0.f, 0.f, 0.f);
    float dpart = 0.f;

    for (int base = 0; base < deg; base += AWIN){
        int cnt = min(AWIN, deg - base);
        if (t < cnt){
            int s = g_csrc[r0 + base + t];
            s_src[t] = s;
            float4 a = ((const float4*)g_asrc)[s];
            float v;
            v = a.x + bdst.x; v = (v > 0.f) ? v : 0.2f * v; s_ex[0][t] = __expf(v);
            v = a.y + bdst.y; v = (v > 0.f) ? v : 0.2f * v; s_ex[1][t] = __expf(v);
            v = a.z + bdst.z; v = (v > 0.f) ? v : 0.2f * v; s_ex[2][t] = __expf(v);
            v = a.w + bdst.w; v = (v > 0.f) ? v : 0.2f * v; s_ex[3][t] = __expf(v);
        }
        __syncthreads();
        // denominator partials: 16 threads per head, stride 16
        for (int j = t & 15; j < cnt; j += 16) dpart += s_ex[hh][j];
        // channel gather (float4 per edge)
        int j = 0;
        for (; j + 4 <= cnt; j += 4){
            int s0 = s_src[j], s1 = s_src[j+1], s2 = s_src[j+2], s3 = s_src[j+3];
            float e0 = s_ex[hh][j],   e1 = s_ex[hh][j+1];
            float e2 = s_ex[hh][j+2], e3 = s_ex[hh][j+3];
            float4 a0 = gh4[s0 * (HH/4) + t];
            float4 a1 = gh4[s1 * (HH/4) + t];
            float4 a2 = gh4[s2 * (HH/4) + t];
            float4 a3 = gh4[s3 * (HH/4) + t];
            acc.x = fmaf(a0.x, e0, acc.x); acc.y = fmaf(a0.y, e0, acc.y);
            acc.z = fmaf(a0.z, e0, acc.z); acc.w = fmaf(a0.w, e0, acc.w);
            acc.x = fmaf(a1.x, e1, acc.x); acc.y = fmaf(a1.y, e1, acc.y);
            acc.z = fmaf(a1.z, e1, acc.z); acc.w = fmaf(a1.w, e1, acc.w);
            acc.x = fmaf(a2.x, e2, acc.x); acc.y = fmaf(a2.y, e2, acc.y);
            acc.z = fmaf(a2.z, e2, acc.z); acc.w = fmaf(a2.w, e2, acc.w);
            acc.x = fmaf(a3.x, e3, acc.x); acc.y = fmaf(a3.y, e3, acc.y);
            acc.z = fmaf(a3.z, e3, acc.z); acc.w = fmaf(a3.w, e3, acc.w);
        }
        for (; j < cnt; j++){
            float e = s_ex[hh][j];
            float4 a0 = gh4[s_src[j] * (HH/4) + t];
            acc.x = fmaf(a0.x, e, acc.x); acc.y = fmaf(a0.y, e, acc.y);
            acc.z = fmaf(a0.z, e, acc.z); acc.w = fmaf(a0.w, e, acc.w);
        }
        __syncthreads();
    }
    // reduce denominator within 16-lane head groups
#pragma unroll
    for (int o = 8; o > 0; o >>= 1)
        dpart += __shfl_down_sync(0xffffffffu, dpart, o, 16);
    if ((t & 15) == 0) s_den[hh] = dpart;
    __syncthreads();

    float den = s_den[hh] + 1e-16f;
    // conv channels: normalize + bias + elu
    float cx = acc.x / den + bgv.x; cx = (cx > 0.f) ? cx : (__expf(cx) - 1.f);
    float cy = acc.y / den + bgv.y; cy = (cy > 0.f) ? cy : (__expf(cy) - 1.f);
    float cz = acc.z / den + bgv.z; cz = (cz > 0.f) ? cz : (__expf(cz) - 1.f);
    float cw = acc.w / den + bgv.w; cw = (cw > 0.f) ? cw : (__expf(cw) - 1.f);
    float aggv = 0.25f * (cx + cy + cz + cw);

    // GraphCON update + rms norms
    float yn = yv + (SP1 * aggv - 2.f * SP1 * SP1 * yv - SP1 * SP1 * xv);
    float xn = xv + yn;
    float px = xn * xn, py = yn * yn;
#pragma unroll
    for (int o = 16; o > 0; o >>= 1){
        px += __shfl_down_sync(0xffffffffu, px, o);
        py += __shfl_down_sync(0xffffffffu, py, o);
    }
    if ((t & 31) == 0){ s_px[t >> 5] = px; s_py[t >> 5] = py; }
    __syncthreads();
    float rx = rsqrtf((s_px[0] + s_px[1]) * (1.f / NHID) + 1e-5f);
    float ry = rsqrtf((s_py[0] + s_py[1]) * (1.f / NHID) + 1e-5f);
    g_X[n * NHID + t] = xn * rx;
    g_Y[n * NHID + t] = yn * ry;
}

// ---------------- decoder: out = X @ W_dec + b_dec ----------------
__global__ void k_decoder(const float* __restrict__ Wd,
                          const float* __restrict__ bd,
                          float* __restrict__ out){
    int gid = blockIdx.x * blockDim.x + threadIdx.x;
    if (gid >= N_NODES * NCLASS) return;
    int n = gid >> 4, j = gid & 15;
    float acc = bd[j];
#pragma unroll
    for (int k = 0; k < NHID; k++)
        acc = fmaf(g_X[n * NHID + k], Wd[k * NCLASS + j], acc);
    out[gid] = acc;
}

extern "C" void kernel_launch(void* const* d_in, const int* in_sizes, int n_in,
                              void* d_out, int out_size){
    const float* x    = (const float*)d_in[0];
    const int*   ei   = (const int*)d_in[1];
    const float* We   = (const float*)d_in[2];
    const float* be   = (const float*)d_in[3];
    const float* Wg   = (const float*)d_in[4];
    const float* atts = (const float*)d_in[5];
    const float* attd = (const float*)d_in[6];
    const float* bg   = (const float*)d_in[7];
    const float* Wd   = (const float*)d_in[8];
    const float* bd   = (const float*)d_in[9];
    float* out = (float*)d_out;

    // CSR build (edges constant across layers)
    k_detect<<<(N_NODES + 255)/256, 256>>>((const unsigned*)ei);
    k_hist<<<(E_TOT + 255)/256, 256>>>(ei);
    k_scan<<<1, 1024>>>();
    k_scatter<<<(E_TOT + 255)/256, 256>>>(ei);
    k_prew<<<1, 512>>>(Wg, atts, attd);

    k_encoder<<<N_NODES/16, 64>>>(x, We, be);
    for (int l = 0; l < 3; l++){
        k_gat_proj<<<N_NODES/32, 256>>>(Wg);
        k_node_agg<<<N_NODES, 64>>>(bg);
    }
    k_decoder<<<(N_NODES*NCLASS + 255)/256, 256>>>(Wd, bd, out);
}

// round 8
// speedup vs baseline: 3.9283x; 1.1705x over previous
#include <cuda_runtime.h>
#include <cuda_fp16.h>
#include <math.h>

#define N_NODES 20000
#define N_EDGES 320000
#define E_TOT   340000   // edges + self loops
#define NFEAT   128
#define NHID    64
#define HEADS   4
#define HH      256      // HEADS*NHID
#define NCLASS  16

// softplus(1.0)
#define SP1 1.3132616875182228f

// ---------------- scratch (device globals, no allocation) ----------------
__device__ int    g_is64;
__device__ int    g_deg[N_NODES];
__device__ int    g_rowptr[N_NODES + 1];
__device__ int    g_cursor[N_NODES];
__device__ int    g_csrc[E_TOT];            // CSR-by-destination source list
__device__ float  g_watt[NHID*8];           // folded attention weights (4 src, 4 dst cols)
__device__ __align__(16) float  g_X[N_NODES*NHID];
__device__ __align__(16) float  g_Y[N_NODES*NHID];
__device__ __align__(16) __half g_h[N_NODES*HH];    // fp16 projected features
__device__ __align__(16) float  g_asrc[N_NODES*HEADS];
__device__ __align__(16) float  g_adst[N_NODES*HEADS];

// decode one edge's (src,dst) from raw edge_index (int32 or int64)
__device__ __forceinline__ void edge_sd(const int* __restrict__ w, int e, int& s, int& d){
    if (e < N_EDGES){
        if (g_is64){ s = w[2*e]; d = w[2*(N_EDGES + e)]; }
        else       { s = w[e];   d = w[N_EDGES + e]; }
    } else {
        s = d = e - N_EDGES;                // self loop
    }
}

// ---------------- dtype detect + zero histogram ----------------
__global__ void k_detect(const unsigned* __restrict__ w){
    int gid = blockIdx.x * blockDim.x + threadIdx.x;
    if (gid < N_NODES) g_deg[gid] = 0;
    if (gid == 0){
        int all0 = 1;
        for (int i = 1; i < 128; i += 2) if (w[i] != 0u) all0 = 0;
        g_is64 = all0;
    }
}

__global__ void k_hist(const int* __restrict__ w){
    int e = blockIdx.x * blockDim.x + threadIdx.x;
    if (e >= E_TOT) return;
    int s, d; edge_sd(w, e, s, d);
    atomicAdd(&g_deg[d], 1);
}

// single-block, single-pass blocked exclusive scan: thread t owns 20 elements
#define SCAN_CH 20
__global__ void k_scan(){
    int t = threadIdx.x, lane = t & 31, w = t >> 5;
    int base = t * SCAN_CH;
    int v[SCAN_CH];
    int sum = 0;
#pragma unroll
    for (int i = 0; i < SCAN_CH; i++){
        int idx = base + i;
        v[i] = (idx < N_NODES) ? g_deg[idx] : 0;
        sum += v[i];
    }
    int s = sum;
#pragma unroll
    for (int off = 1; off < 32; off <<= 1){
        int n = __shfl_up_sync(0xffffffffu, s, off);
        if (lane >= off) s += n;
    }
    __shared__ int wtot[32];
    if (lane == 31) wtot[w] = s;
    __syncthreads();
    if (w == 0){
        int ws = wtot[lane];
#pragma unroll
        for (int off = 1; off < 32; off <<= 1){
            int n = __shfl_up_sync(0xffffffffu, ws, off);
            if (lane >= off) ws += n;
        }
        wtot[lane] = ws;
    }
    __syncthreads();
    int excl = (s - sum) + (w > 0 ? wtot[w - 1] : 0);
    int run = excl;
#pragma unroll
    for (int i = 0; i < SCAN_CH; i++){
        int idx = base + i;
        if (idx < N_NODES){ g_rowptr[idx] = run; g_cursor[idx] = run; }
        run += v[i];
    }
    if (t == 1023) g_rowptr[N_NODES] = run;
}

__global__ void k_scatter(const int* __restrict__ w){
    int e = blockIdx.x * blockDim.x + threadIdx.x;
    if (e >= E_TOT) return;
    int s, d; edge_sd(w, e, s, d);
    int pos = atomicAdd(&g_cursor[d], 1);
    g_csrc[pos] = s;
}

// ---------------- fold attention vectors through W_gat: w_att = Wg @ [atts|attd] ----------------
__global__ void k_prew(const float* __restrict__ Wg,
                       const float* __restrict__ atts,
                       const float* __restrict__ attd){
    int t = threadIdx.x;
    int k = t >> 3, o = t & 7;
    const float* av = (o < 4) ? (atts + (o & 3) * NHID) : (attd + (o & 3) * NHID);
    const float* wr = Wg + k * HH + (o & 3) * NHID;
    float a = 0.f;
#pragma unroll 8
    for (int f = 0; f < NHID; f++) a = fmaf(wr[f], av[f], a);
    g_watt[k * 8 + o] = a;
}

// ---------------- encoder: Y = relu(x @ W_enc + b_enc); X = Y ----------------
__global__ void k_encoder(const float* __restrict__ x,
                          const float* __restrict__ We,
                          const float* __restrict__ be){
    int nb = blockIdx.x * 16;
    int t  = threadIdx.x;
    __shared__ float4 xs4[16][NFEAT/4];
    for (int r = t; r < 16 * (NFEAT/4); r += 64)
        xs4[r >> 5][r & 31] = ((const float4*)x)[(nb + (r >> 5)) * (NFEAT/4) + (r & 31)];
    __syncthreads();
    float acc[16];
    float b = be[t];
#pragma unroll
    for (int m = 0; m < 16; m++) acc[m] = b;
    for (int k4 = 0; k4 < NFEAT/4; k4++){
        float w0 = We[(4*k4+0) * NHID + t];
        float w1 = We[(4*k4+1) * NHID + t];
        float w2 = We[(4*k4+2) * NHID + t];
        float w3 = We[(4*k4+3) * NHID + t];
#pragma unroll
        for (int m = 0; m < 16; m++){
            float4 xv = xs4[m][k4];
            acc[m] = fmaf(xv.x, w0, acc[m]);
            acc[m] = fmaf(xv.y, w1, acc[m]);
            acc[m] = fmaf(xv.z, w2, acc[m]);
            acc[m] = fmaf(xv.w, w3, acc[m]);
        }
    }
#pragma unroll
    for (int m = 0; m < 16; m++){
        float v = fmaxf(acc[m], 0.f);
        g_Y[(nb + m) * NHID + t] = v;
        g_X[(nb + m) * NHID + t] = v;
    }
}

// ---------------- per-layer projection: h = X @ W_gat (+ folded a_src/a_dst) ----------------
// 32 nodes per block, 256 threads (thread = output column), float4 k-loop, fp16 h output
__global__ void k_gat_proj(const float* __restrict__ Wg){
    int nb = blockIdx.x * 32;
    int t  = threadIdx.x;
    __shared__ float4 xs4[32][NHID/4];   // 8KB
    __shared__ float  watt[NHID*8];      // 2KB
    for (int r = t; r < 32 * (NHID/4); r += 256)
        xs4[r >> 4][r & 15] = ((const float4*)g_X)[(nb + (r >> 4)) * (NHID/4) + (r & 15)];
    for (int r = t; r < NHID*8; r += 256) watt[r] = g_watt[r];
    __syncthreads();
    float acc[32];
#pragma unroll
    for (int m = 0; m < 32; m++) acc[m] = 0.f;
    for (int k4 = 0; k4 < NHID/4; k4++){
        float w0 = Wg[(4*k4+0) * HH + t];
        float w1 = Wg[(4*k4+1) * HH + t];
        float w2 = Wg[(4*k4+2) * HH + t];
        float w3 = Wg[(4*k4+3) * HH + t];
#pragma unroll
        for (int m = 0; m < 32; m++){
            float4 xv = xs4[m][k4];
            acc[m] = fmaf(xv.x, w0, acc[m]);
            acc[m] = fmaf(xv.y, w1, acc[m]);
            acc[m] = fmaf(xv.z, w2, acc[m]);
            acc[m] = fmaf(xv.w, w3, acc[m]);
        }
    }
    // pack adjacent columns into half2 via shfl, even threads store
#pragma unroll
    for (int m = 0; m < 32; m++){
        float other = __shfl_xor_sync(0xffffffffu, acc[m], 1);
        if (!(t & 1)){
            __half2 hv = __floats2half2_rn(acc[m], other);
            ((__half2*)g_h)[((nb + m) * HH + t) >> 1] = hv;
        }
    }

    // attention scores: 256 threads = 32 nodes x 8 outputs
    int m = t >> 3, o = t & 7;
    const float* xr = (const float*)&xs4[m][0];
    float a = 0.f;
#pragma unroll 8
    for (int k = 0; k < NHID; k++) a = fmaf(xr[k], watt[k * 8 + o], a);
    if (o < 4) g_asrc[(nb + m) * HEADS + o] = a;
    else       g_adst[(nb + m) * HEADS + (o - 4)] = a;
}

// ---------------- fused per-node: attention + gather + normalize + GraphCON ----------------
// one block = one WARP = one destination node; thread t owns channels 8t..8t+7
// (all in head t>>3; hidden units 2t and 2t+1)
// softmax without max-subtraction: ratios identical, |e| is small so exp is safe
__global__ void k_node_agg(const float* __restrict__ bg){
    int n = blockIdx.x;
    int t = threadIdx.x;                 // 0..31
    int hh = t >> 3;                     // head of this thread's channels
    int r0 = g_rowptr[n], deg = g_rowptr[n+1] - r0;

    __shared__ int   s_src[32];
    __shared__ float s_ex[HEADS][32];

    // prefetch epilogue operands (hide behind gather)
    float2 xv = ((const float2*)g_X)[n * 32 + t];
    float2 yv = ((const float2*)g_Y)[n * 32 + t];
    float4 bg0 = ((const float4*)bg)[2*t];
    float4 bg1 = ((const float4*)bg)[2*t + 1];
    float4 bdst = ((const float4*)g_adst)[n];

    const uint4* gh = (const uint4*)g_h;   // 8 halves per uint4; row stride HH/8 = 32
    float acc[8];
#pragma unroll
    for (int i = 0; i < 8; i++) acc[i] = 0.f;
    float dpart = 0.f;

    for (int base = 0; base < deg; base += 32){
        int cnt = min(32, deg - base);
        if (t < cnt){
            int s = g_csrc[r0 + base + t];
            s_src[t] = s;
            float4 a = ((const float4*)g_asrc)[s];
            float v;
            v = a.x + bdst.x; v = (v > 0.f) ? v : 0.2f * v; s_ex[0][t] = __expf(v);
            v = a.y + bdst.y; v = (v > 0.f) ? v : 0.2f * v; s_ex[1][t] = __expf(v);
            v = a.z + bdst.z; v = (v > 0.f) ? v : 0.2f * v; s_ex[2][t] = __expf(v);
            v = a.w + bdst.w; v = (v > 0.f) ? v : 0.2f * v; s_ex[3][t] = __expf(v);
        }
        __syncwarp();
        for (int j = t & 7; j < cnt; j += 8) dpart += s_ex[hh][j];
        for (int j = 0; j < cnt; j++){
            float e = s_ex[hh][j];
            uint4 hv = gh[s_src[j] * 32 + t];
            float2 f0 = __half22float2(*(const __half2*)&hv.x);
            float2 f1 = __half22float2(*(const __half2*)&hv.y);
            float2 f2 = __half22float2(*(const __half2*)&hv.z);
            float2 f3 = __half22float2(*(const __half2*)&hv.w);
            acc[0] = fmaf(f0.x, e, acc[0]); acc[1] = fmaf(f0.y, e, acc[1]);
            acc[2] = fmaf(f1.x, e, acc[2]); acc[3] = fmaf(f1.y, e, acc[3]);
            acc[4] = fmaf(f2.x, e, acc[4]); acc[5] = fmaf(f2.y, e, acc[5]);
            acc[6] = fmaf(f3.x, e, acc[6]); acc[7] = fmaf(f3.y, e, acc[7]);
        }
        __syncwarp();
    }
    // reduce denominator within 8-lane head groups, then broadcast group base
#pragma unroll
    for (int o = 4; o > 0; o >>= 1)
        dpart += __shfl_down_sync(0xffffffffu, dpart, o, 8);
    float den = __shfl_sync(0xffffffffu, dpart, t & 24) + 1e-16f;
    float rden = 1.f / den;

    // conv channels: normalize + bias + elu; means for hidden units 2t, 2t+1
    float c0 = fmaf(acc[0], rden, bg0.x); c0 = (c0 > 0.f) ? c0 : (__expf(c0) - 1.f);
    float c1 = fmaf(acc[1], rden, bg0.y); c1 = (c1 > 0.f) ? c1 : (__expf(c1) - 1.f);
    float c2 = fmaf(acc[2], rden, bg0.z); c2 = (c2 > 0.f) ? c2 : (__expf(c2) - 1.f);
    float c3 = fmaf(acc[3], rden, bg0.w); c3 = (c3 > 0.f) ? c3 : (__expf(c3) - 1.f);
    float c4 = fmaf(acc[4], rden, bg1.x); c4 = (c4 > 0.f) ? c4 : (__expf(c4) - 1.f);
    float c5 = fmaf(acc[5], rden, bg1.y); c5 = (c5 > 0.f) ? c5 : (__expf(c5) - 1.f);
    float c6 = fmaf(acc[6], rden, bg1.z); c6 = (c6 > 0.f) ? c6 : (__expf(c6) - 1.f);
    float c7 = fmaf(acc[7], rden, bg1.w); c7 = (c7 > 0.f) ? c7 : (__expf(c7) - 1.f);
    float agg0 = 0.25f * (c0 + c1 + c2 + c3);
    float agg1 = 0.25f * (c4 + c5 + c6 + c7);

    // GraphCON update on hidden units 2t, 2t+1
    float yn0 = yv.x + (SP1 * agg0 - 2.f * SP1 * SP1 * yv.x - SP1 * SP1 * xv.x);
    float xn0 = xv.x + yn0;
    float yn1 = yv.y + (SP1 * agg1 - 2.f * SP1 * SP1 * yv.y - SP1 * SP1 * xv.y);
    float xn1 = xv.y + yn1;

    // rms norms over all 64 hidden units (warp-wide shuffle reduce, xor = all lanes get it)
    float px = xn0 * xn0 + xn1 * xn1;
    float py = yn0 * yn0 + yn1 * yn1;
#pragma unroll
    for (int o = 16; o > 0; o >>= 1){
        px += __shfl_xor_sync(0xffffffffu, px, o);
        py += __shfl_xor_sync(0xffffffffu, py, o);
    }
    float rx = rsqrtf(px * (1.f / NHID) + 1e-5f);
    float ry = rsqrtf(py * (1.f / NHID) + 1e-5f);
    float2 xo = make_float2(xn0 * rx, xn1 * rx);
    float2 yo = make_float2(yn0 * ry, yn1 * ry);
    ((float2*)g_X)[n * 32 + t] = xo;
    ((float2*)g_Y)[n * 32 + t] = yo;
}

// ---------------- decoder: out = X @ W_dec + b_dec ----------------
__global__ void k_decoder(const float* __restrict__ Wd,
                          const float* __restrict__ bd,
                          float* __restrict__ out){
    int gid = blockIdx.x * blockDim.x + threadIdx.x;
    if (gid >= N_NODES * NCLASS) return;
    int n = gid >> 4, j = gid & 15;
    float acc = bd[j];
#pragma unroll
    for (int k = 0; k < NHID; k++)
        acc = fmaf(g_X[n * NHID + k], Wd[k * NCLASS + j], acc);
    out[gid] = acc;
}

extern "C" void kernel_launch(void* const* d_in, const int* in_sizes, int n_in,
                              void* d_out, int out_size){
    const float* x    = (const float*)d_in[0];
    const int*   ei   = (const int*)d_in[1];
    const float* We   = (const float*)d_in[2];
    const float* be   = (const float*)d_in[3];
    const float* Wg   = (const float*)d_in[4];
    const float* atts = (const float*)d_in[5];
    const float* attd = (const float*)d_in[6];
    const float* bg   = (const float*)d_in[7];
    const float* Wd   = (const float*)d_in[8];
    const float* bd   = (const float*)d_in[9];
    float* out = (float*)d_out;

    // CSR build (edges constant across layers)
    k_detect<<<(N_NODES + 255)/256, 256>>>((const unsigned*)ei);
    k_hist<<<(E_TOT + 255)/256, 256>>>(ei);
    k_scan<<<1, 1024>>>();
    k_scatter<<<(E_TOT + 255)/256, 256>>>(ei);
    k_prew<<<1, 512>>>(Wg, atts, attd);

    k_encoder<<<N_NODES/16, 64>>>(x, We, be);
    for (int l = 0; l < 3; l++){
        k_gat_proj<<<N_NODES/32, 256>>>(Wg);
        k_node_agg<<<N_NODES, 32>>>(bg);
    }
    k_decoder<<<(N_NODES*NCLASS + 255)/256, 256>>>(Wd, bd, out);
}